// round 11
// baseline (speedup 1.0000x reference)
#include <cuda_runtime.h>
#include <cstdint>

namespace {
constexpr int H = 64, W = 64;
constexpr int C = 384;   // 48 positions * 8 channels
constexpr int B = 32;
constexpr int PLANES = B * C;          // 12288
}

// 5-tap normalized gaussian from fractional offset sub, sigma=0.5.
__device__ __forceinline__ void gauss5(float sub, float w[5]) {
  const float c1 = 0.135335283236612692f;    // exp(-2)
  const float c2 = 3.35462627902511839e-4f;  // exp(-8)
  float t  = __expf(-4.0f * sub);
  float it = 1.0f / t;
  float e0 = c2 * it * it;
  float e1 = c1 * it;
  float e2 = 1.0f;
  float e3 = c1 * t;
  float e4 = c2 * t * t;
  float inv = 1.0f / (e0 + e1 + e2 + e3 + e4);
  w[0] = e0 * inv; w[1] = e1 * inv; w[2] = e2 * inv;
  w[3] = e3 * inv; w[4] = e4 * inv;
}

// 256-bit L2-persistent read-only load (32B-aligned address required).
__device__ __forceinline__ void ldg_v8_el(const float* p, float v[8]) {
  uint32_t r0, r1, r2, r3, r4, r5, r6, r7;
  asm("ld.global.nc.L2::evict_last.v8.b32 {%0,%1,%2,%3,%4,%5,%6,%7}, [%8];"
      : "=r"(r0), "=r"(r1), "=r"(r2), "=r"(r3),
        "=r"(r4), "=r"(r5), "=r"(r6), "=r"(r7) : "l"(p));
  v[0] = __uint_as_float(r0); v[1] = __uint_as_float(r1);
  v[2] = __uint_as_float(r2); v[3] = __uint_as_float(r3);
  v[4] = __uint_as_float(r4); v[5] = __uint_as_float(r5);
  v[6] = __uint_as_float(r6); v[7] = __uint_as_float(r7);
}

__global__ __launch_bounds__(128) void displace_gauss_kernel(
    const float* __restrict__ x, const float* __restrict__ offset,
    float* __restrict__ out) {
  const int tid  = threadIdx.x;
  const int gw   = (blockIdx.x * 128 + tid) >> 5;  // global warp id
  const int lane = tid & 31;
  const int pg   = gw >> 4;            // plane group of 4 (same offset group)
  const int yb   = gw & 15;            // y-band 0..15 (4 rows each)
  const int y0   = yb * 4;
  const int q    = lane >> 3;          // plane within group
  const int lq   = lane & 7;           // col group of 8 within plane
  const int x0   = lq * 8;
  const int plane = pg * 4 + q;
  const int p = (plane % C) >> 3;      // all 4 planes share p (4 | 8)

  const float ox = __ldg(&offset[2 * p + 0]);
  const float oy = __ldg(&offset[2 * p + 1]);
  const float rxv = rintf(ox), ryv = rintf(oy);   // matches jnp.round
  const int dx = (int)rxv, dy = (int)ryv;

  float* __restrict__ dst = out + (size_t)plane * (H * W) + y0 * W + x0;

  // warp-uniform y-liveness: tap rows y0-2..y0+5 must hit a valid source row
  if ((y0 + 5 - dy < 0) || (y0 - 2 - dy > H - 1)) {
    const float4 z = make_float4(0.f, 0.f, 0.f, 0.f);
#pragma unroll
    for (int o = 0; o < 4; o++) {
      __stcs(reinterpret_cast<float4*>(dst + o * W), z);
      __stcs(reinterpret_cast<float4*>(dst + o * W + 4), z);
    }
    return;
  }

  float wx[5], wy[5];
  gauss5(ox - rxv, wx);
  gauss5(oy - ryv, wy);

  const float* __restrict__ src = x + (size_t)plane * (H * W);

  float acc[4][8];
#pragma unroll
  for (int o = 0; o < 4; o++)
#pragma unroll
    for (int u = 0; u < 8; u++) acc[o][u] = 0.f;

  if ((dx & 7) == 0) {
    // fast path (this problem: dx multiples of 16). Main v8 load is 32B
    // aligned (x0%8==0, dx%8==0). Validity = conv padding AND source range;
    // all-or-none per vector since region edges are multiples of 8 resp. 4.
    const int sxv = x0 - dx;           // source col of main v8, mult of 8
    const bool okm =               ((unsigned)sxv       <= (unsigned)(W - 8));
    const bool okl = (lq != 0) &&  ((unsigned)(sxv - 4) <= (unsigned)(W - 4));
    const bool okr = (lq != 7) &&  ((unsigned)(sxv + 8) <= (unsigned)(W - 4));
#pragma unroll
    for (int r = 0; r < 8; r++) {
      const int pr = y0 - 2 + r;       // displaced (conv tap) row
      const bool syok = ((unsigned)pr < (unsigned)H) &&
                        ((unsigned)(pr - dy) < (unsigned)H);
      const float* rowp = src + (pr - dy) * W;
      float t[12];                     // disp cols x0-2 .. x0+9
      float m[8] = {0.f,0.f,0.f,0.f,0.f,0.f,0.f,0.f};
      float4 lft = make_float4(0.f, 0.f, 0.f, 0.f);
      float4 rgt = make_float4(0.f, 0.f, 0.f, 0.f);
      if (syok && okm) ldg_v8_el(rowp + sxv, m);
      if (syok && okl) lft = __ldg(reinterpret_cast<const float4*>(rowp + sxv - 4));
      if (syok && okr) rgt = __ldg(reinterpret_cast<const float4*>(rowp + sxv + 8));
      t[0] = lft.z; t[1] = lft.w;
#pragma unroll
      for (int u = 0; u < 8; u++) t[2 + u] = m[u];
      t[10] = rgt.x; t[11] = rgt.y;
      float h[8];
#pragma unroll
      for (int u = 0; u < 8; u++)
        h[u] = wx[0]*t[u] + wx[1]*t[u+1] + wx[2]*t[u+2]
             + wx[3]*t[u+3] + wx[4]*t[u+4];
#pragma unroll
      for (int o = 0; o < 4; o++) {
        int i = r - o;                 // compile-time pruned
        if (i >= 0 && i < 5) {
          float wv = wy[i];
#pragma unroll
          for (int u = 0; u < 8; u++) acc[o][u] += wv * h[u];
        }
      }
    }
  } else {
    // generic scalar fallback (not taken for this problem's offset grid)
#pragma unroll
    for (int r = 0; r < 8; r++) {
      const int pr = y0 - 2 + r;
      const bool syok = ((unsigned)pr < (unsigned)H) &&
                        ((unsigned)(pr - dy) < (unsigned)H);
      const float* rowp = src + (pr - dy) * W;
      float t[12];
#pragma unroll
      for (int u = 0; u < 12; u++) {   // displaced cols x0-2 .. x0+9
        const int pc = x0 - 2 + u;
        t[u] = 0.f;
        if (syok && (unsigned)pc < (unsigned)W &&
            (unsigned)(pc - dx) < (unsigned)W)
          t[u] = rowp[pc - dx];
      }
      float h[8];
#pragma unroll
      for (int u = 0; u < 8; u++)
        h[u] = wx[0]*t[u] + wx[1]*t[u+1] + wx[2]*t[u+2]
             + wx[3]*t[u+3] + wx[4]*t[u+4];
#pragma unroll
      for (int o = 0; o < 4; o++) {
        int i = r - o;
        if (i >= 0 && i < 5) {
          float wv = wy[i];
#pragma unroll
          for (int u = 0; u < 8; u++) acc[o][u] += wv * h[u];
        }
      }
    }
  }

#pragma unroll
  for (int o = 0; o < 4; o++) {
    __stcs(reinterpret_cast<float4*>(dst + o * W),
           make_float4(acc[o][0], acc[o][1], acc[o][2], acc[o][3]));
    __stcs(reinterpret_cast<float4*>(dst + o * W + 4),
           make_float4(acc[o][4], acc[o][5], acc[o][6], acc[o][7]));
  }
}

extern "C" void kernel_launch(void* const* d_in, const int* in_sizes, int n_in,
                              void* d_out, int out_size) {
  const float* x = (const float*)d_in[0];
  const float* offset = (const float*)d_in[1];
  float* out = (float*)d_out;
  // warps = (PLANES/4 groups) * 16 y-bands; 4 warps per 128-thread CTA
  displace_gauss_kernel<<<(PLANES / 4) * 16 / 4, 128>>>(x, offset, out);
}

// round 12
// speedup vs baseline: 1.0309x; 1.0309x over previous
#include <cuda_runtime.h>

namespace {
constexpr int H = 64, W = 64;
constexpr int C = 384;   // 48 positions * 8 channels
constexpr int B = 32;
constexpr int AP = 72;   // smem row pitch (floats), 288B -> 16B-aligned rows
constexpr int AR = 68;   // logical rows/cols of padded+displaced tile
}

// 5-tap normalized gaussian from fractional offset sub, sigma=0.5.
// e_j ∝ exp(-2(j-2)^2) * t^(j-2), t = exp(-4*sub); common factor cancels.
__device__ __forceinline__ void gauss5(float sub, float w[5]) {
  const float c1 = 0.135335283236612692f;    // exp(-2)
  const float c2 = 3.35462627902511839e-4f;  // exp(-8)
  float t  = __expf(-4.0f * sub);
  float it = 1.0f / t;
  float e0 = c2 * it * it;
  float e1 = c1 * it;
  float e2 = 1.0f;
  float e3 = c1 * t;
  float e4 = c2 * t * t;
  float inv = 1.0f / (e0 + e1 + e2 + e3 + e4);
  w[0] = e0 * inv; w[1] = e1 * inv; w[2] = e2 * inv;
  w[3] = e3 * inv; w[4] = e4 * inv;
}

// 256-bit L2-persistent read-only load (32B-aligned address required).
__device__ __forceinline__ void ldg_v8_el(const float* p, float v[8]) {
  asm("ld.global.nc.L2::evict_last.v8.b32 {%0,%1,%2,%3,%4,%5,%6,%7}, [%8];"
      : "=f"(v[0]), "=f"(v[1]), "=f"(v[2]), "=f"(v[3]),
        "=f"(v[4]), "=f"(v[5]), "=f"(v[6]), "=f"(v[7]) : "l"(p));
}

__global__ __launch_bounds__(256, 6) void displace_gauss_kernel(
    const float* __restrict__ x, const float* __restrict__ offset,
    float* __restrict__ out) {
  __shared__ __align__(16) float A[AR * AP];
  __shared__ float swx[5], swy[5];

  const int plane = blockIdx.x;         // b*C + c
  const int c = plane % C;
  const int p = c >> 3;                 // 8 channels per position
  const int tid = threadIdx.x;

  // --- every thread computes integer offset itself (broadcast loads) ---
  const float ox = __ldg(&offset[2 * p + 0]);
  const float oy = __ldg(&offset[2 * p + 1]);
  const float rxv = rintf(ox), ryv = rintf(oy);   // matches jnp.round
  const int dx = (int)rxv;
  const int dy = (int)ryv;

  // --- Gaussian weights: lane 0 does x-axis, lane 1 does y-axis ---
  if (tid < 2) {
    float w[5];
    gauss5((tid == 0) ? (ox - rxv) : (oy - ryv), w);
    float* d = (tid == 0) ? swx : swy;
#pragma unroll
    for (int j = 0; j < 5; j++) d[j] = w[j];
  }

  // --- zero the 2-wide halo (always zero: px/py out of [0,64) there) ---
  if (tid < AR) {
    A[0 * AP + tid] = 0.f;  A[1 * AP + tid] = 0.f;
    A[66 * AP + tid] = 0.f; A[67 * AP + tid] = 0.f;
    float* row = &A[tid * AP];
    row[0] = 0.f; row[1] = 0.f; row[66] = 0.f; row[67] = 0.f;
  }

  // --- fill 64x64 interior ---
  const float* __restrict__ src = x + (size_t)plane * (H * W);
  const int g    = tid & 7;             // col group of 8: px = 8g
  const int row0 = tid >> 3;            // rows row0, row0+32
  const int px = g * 8;

  if ((dx & 7) == 0) {
    // vector path (this problem: dx multiples of 16): displaced v8 stays
    // 32B-aligned and validity is all-or-none (region edges mult of 8).
    const int sx = px - dx;             // multiple of 8
    const bool sxok = (unsigned)sx <= (unsigned)(W - 8);
#pragma unroll
    for (int i = 0; i < 2; i++) {
      const int py = row0 + i * 32;
      const int sy = py - dy;
      float v[8] = {0.f,0.f,0.f,0.f,0.f,0.f,0.f,0.f};
      if (sxok && (unsigned)sy < (unsigned)H)
        ldg_v8_el(&src[sy * W + sx], v);
      float* d = &A[(2 + py) * AP + 2 + px];   // 8B-aligned
      *reinterpret_cast<float2*>(d + 0) = make_float2(v[0], v[1]);
      *reinterpret_cast<float2*>(d + 2) = make_float2(v[2], v[3]);
      *reinterpret_cast<float2*>(d + 4) = make_float2(v[4], v[5]);
      *reinterpret_cast<float2*>(d + 6) = make_float2(v[6], v[7]);
    }
  } else {
    // generic scalar path (not taken for this problem's offset grid)
#pragma unroll
    for (int i = 0; i < 2; i++) {
      const int py = row0 + i * 32;
      const int sy = py - dy;
      const bool syok = (unsigned)sy < (unsigned)H;
      float* d = &A[(2 + py) * AP + 2 + px];
#pragma unroll
      for (int u = 0; u < 8; u++) {
        const int sxu = px + u - dx;
        float v = 0.f;
        if (syok && (unsigned)sxu < (unsigned)W) v = __ldg(&src[sy * W + sxu]);
        d[u] = v;
      }
    }
  }
  __syncthreads();                      // single barrier

  // --- per-thread output tile coordinates (4 wide x 4 tall) ---
  const int txi = tid & 15;             // 16 x-tiles of width 4
  const int tyi = tid >> 4;             // 16 y-tiles of height 4
  const int x0 = txi * 4;
  const int y0 = tyi * 4;
  float* __restrict__ dst = out + (size_t)plane * (H * W);

  // --- liveness: does this tile's input window touch any valid pixel? ---
  {
    const int cx0 = dx > 0 ? dx : 0;
    const int cx1 = dx < 0 ? (W - 1 + dx) : (W - 1);
    const int cy0 = dy > 0 ? dy : 0;
    const int cy1 = dy < 0 ? (H - 1 + dy) : (H - 1);
    const bool live = (x0 + 5 >= cx0) & (x0 - 2 <= cx1) &
                      (y0 + 5 >= cy0) & (y0 - 2 <= cy1);
    if (!live) {                        // entire tile is exactly zero
      const float4 z = make_float4(0.f, 0.f, 0.f, 0.f);
#pragma unroll
      for (int o = 0; o < 4; o++)
        __stcs(reinterpret_cast<float4*>(&dst[(y0 + o) * W + x0]), z);
      return;                           // no more barriers follow
    }
  }

  const float wx0 = swx[0], wx1 = swx[1], wx2 = swx[2], wx3 = swx[3], wx4 = swx[4];
  float wy[5];
#pragma unroll
  for (int i = 0; i < 5; i++) wy[i] = swy[i];

  // --- separable conv, 4x4 outputs per thread, register row-sliding ---
  float acc[4][4];
#pragma unroll
  for (int o = 0; o < 4; o++)
#pragma unroll
    for (int u = 0; u < 4; u++) acc[o][u] = 0.f;

#pragma unroll
  for (int r = 0; r < 8; r++) {         // 8 h-rows feed 4 output rows
    const float* row = &A[(y0 + r) * AP + x0];
    float4 a0 = *reinterpret_cast<const float4*>(row);
    float4 a1 = *reinterpret_cast<const float4*>(row + 4);
    float a[8] = {a0.x, a0.y, a0.z, a0.w, a1.x, a1.y, a1.z, a1.w};
    float h[4];
#pragma unroll
    for (int u = 0; u < 4; u++)
      h[u] = wx0 * a[u] + wx1 * a[u + 1] + wx2 * a[u + 2]
           + wx3 * a[u + 3] + wx4 * a[u + 4];
#pragma unroll
    for (int o = 0; o < 4; o++) {
      int i = r - o;                    // compile-time pruned
      if (i >= 0 && i < 5) {
        float wv = wy[i];
#pragma unroll
        for (int u = 0; u < 4; u++) acc[o][u] += wv * h[u];
      }
    }
  }

#pragma unroll
  for (int o = 0; o < 4; o++) {
    float4 v = make_float4(acc[o][0], acc[o][1], acc[o][2], acc[o][3]);
    __stcs(reinterpret_cast<float4*>(&dst[(y0 + o) * W + x0]), v);
  }
}

extern "C" void kernel_launch(void* const* d_in, const int* in_sizes, int n_in,
                              void* d_out, int out_size) {
  const float* x = (const float*)d_in[0];
  const float* offset = (const float*)d_in[1];
  float* out = (float*)d_out;
  displace_gauss_kernel<<<B * C, 256>>>(x, offset, out);
}